// round 1
// baseline (speedup 1.0000x reference)
#include <cuda_runtime.h>

#define N_NODES 50000
#define N_EDGES 600000
#define D 128
#define BM 64
#define BK 32

// Scratch (allocation-free rule: __device__ globals)
__device__ float g_agg[N_NODES * D];   // 25.6 MB accumulator
__device__ float g_deg[N_NODES];       // in-degree
__device__ float g_Wt[2 * D * D];      // W transposed: [k][j], k in 0..255, j in 0..127

// ---------------------------------------------------------------------------
// Zero the accumulator + degree arrays (grid-stride, vectorized)
// ---------------------------------------------------------------------------
__global__ void zero_kernel() {
    int idx = blockIdx.x * blockDim.x + threadIdx.x;
    int stride = gridDim.x * blockDim.x;
    const int total4 = (N_NODES * D) / 4;
    float4 z4 = make_float4(0.f, 0.f, 0.f, 0.f);
    for (int i = idx; i < total4; i += stride)
        ((float4*)g_agg)[i] = z4;
    for (int i = idx; i < N_NODES; i += stride)
        g_deg[i] = 0.f;
}

// ---------------------------------------------------------------------------
// Transpose W [128, 256] row-major -> Wt [256, 128]
// ---------------------------------------------------------------------------
__global__ void transpose_kernel(const float* __restrict__ W) {
    int idx = blockIdx.x * blockDim.x + threadIdx.x;   // 0 .. 32767
    if (idx < 2 * D * D) {
        int k = idx >> 7;       // 0..255
        int j = idx & 127;      // 0..127
        g_Wt[idx] = W[j * 2 * D + k];
    }
}

// ---------------------------------------------------------------------------
// Scatter: one warp per edge. lane l handles features [4l, 4l+4).
// Index dtype (int32 vs int64) detected on-device: values are < 50000, so if
// the data is int64 (little-endian), every odd 32-bit word is 0.
// ---------------------------------------------------------------------------
__global__ void scatter_kernel(const float* __restrict__ nf,
                               const float* __restrict__ ew,
                               const int*   __restrict__ src32,
                               const int*   __restrict__ dst32) {
    int gwarp = (blockIdx.x * blockDim.x + threadIdx.x) >> 5;
    int lane  = threadIdx.x & 31;
    if (gwarp >= N_EDGES) return;

    // dtype detection (cheap, L1-cached, identical result for all warps)
    bool is64 = ((src32[1] | src32[3] | src32[5] | src32[7]) == 0);

    long long s, d;
    if (is64) {
        s = ((const long long*)src32)[gwarp];
        d = ((const long long*)dst32)[gwarp];
    } else {
        s = (long long)src32[gwarp];
        d = (long long)dst32[gwarp];
    }

    float w = ew[gwarp];
    float4 v = ((const float4*)nf)[s * (D / 4) + lane];
    float* out = g_agg + d * D + lane * 4;
    atomicAdd(out + 0, v.x * w);
    atomicAdd(out + 1, v.y * w);
    atomicAdd(out + 2, v.z * w);
    atomicAdd(out + 3, v.w * w);
    if (lane == 0)
        atomicAdd(g_deg + d, 1.0f);
}

// ---------------------------------------------------------------------------
// GEMM: out[n][j] = sum_k z[n][k] * Wt[k][j] + b[j]
//   z[n][k] = (k < 128) ? agg[n][k] / max(deg[n],1) : nf[n][k-128]
// Tile: 64 nodes x 128 cols per block, 256 threads.
// warp w owns node rows [8w, 8w+8); lane l owns cols [4l, 4l+4).
// Shared: zs[64][33] (padded, conflict-free scalar broadcast reads)
//         ws[32][128] (float4 reads, conflict-free)
// ---------------------------------------------------------------------------
__global__ __launch_bounds__(256, 4)
void gemm_kernel(const float* __restrict__ nf,
                 const float* __restrict__ bias,
                 float* __restrict__ out) {
    __shared__ float zs[BM][BK + 1];
    __shared__ float ws[BK][D];

    int tx   = threadIdx.x;
    int lane = tx & 31;
    int rg   = tx >> 5;          // warp id = node row group
    int n0   = blockIdx.x * BM;

    float acc[8][4];
    #pragma unroll
    for (int i = 0; i < 8; i++)
        #pragma unroll
        for (int c = 0; c < 4; c++) acc[i][c] = 0.f;

    for (int kt = 0; kt < (2 * D) / BK; kt++) {
        int k0 = kt * BK;
        __syncthreads();   // protect prior-iter shared reads

        // ---- load zs: 64 nodes x 32 k = 512 float4, 2 per thread ----
        #pragma unroll
        for (int r = 0; r < 2; r++) {
            int i    = tx + r * 256;
            int node = i >> 3;          // 0..63
            int kq   = i & 7;           // float4 slot within the 32-k tile
            int n    = n0 + node;
            int nn   = (n < N_NODES) ? n : 0;   // clamp (stores are guarded)
            float4 v;
            if (k0 < D) {
                v = *(const float4*)(g_agg + (long long)nn * D + k0 + kq * 4);
                float inv = 1.0f / fmaxf(g_deg[nn], 1.0f);
                v.x *= inv; v.y *= inv; v.z *= inv; v.w *= inv;
            } else {
                v = *(const float4*)(nf + (long long)nn * D + (k0 - D) + kq * 4);
            }
            zs[node][kq * 4 + 0] = v.x;
            zs[node][kq * 4 + 1] = v.y;
            zs[node][kq * 4 + 2] = v.z;
            zs[node][kq * 4 + 3] = v.w;
        }

        // ---- load ws: 32 k x 128 j = 1024 float4, 4 per thread ----
        #pragma unroll
        for (int r = 0; r < 4; r++) {
            int i  = tx + r * 256;
            int k  = i >> 5;            // 0..31
            int jq = i & 31;            // float4 slot across 128 cols
            float4 v = *(const float4*)(g_Wt + (long long)(k0 + k) * D + jq * 4);
            *(float4*)(&ws[k][jq * 4]) = v;
        }
        __syncthreads();

        // ---- inner product ----
        #pragma unroll 4
        for (int kk = 0; kk < BK; kk++) {
            float4 wv = *(const float4*)(&ws[kk][lane * 4]);
            #pragma unroll
            for (int i = 0; i < 8; i++) {
                float zv = zs[rg * 8 + i][kk];
                acc[i][0] += zv * wv.x;
                acc[i][1] += zv * wv.y;
                acc[i][2] += zv * wv.z;
                acc[i][3] += zv * wv.w;
            }
        }
    }

    // ---- epilogue: add bias, store ----
    float4 bv = *(const float4*)(bias + lane * 4);
    #pragma unroll
    for (int i = 0; i < 8; i++) {
        int n = n0 + rg * 8 + i;
        if (n < N_NODES) {
            float4 o;
            o.x = acc[i][0] + bv.x;
            o.y = acc[i][1] + bv.y;
            o.z = acc[i][2] + bv.z;
            o.w = acc[i][3] + bv.w;
            *(float4*)(out + (long long)n * D + lane * 4) = o;
        }
    }
}

// ---------------------------------------------------------------------------
extern "C" void kernel_launch(void* const* d_in, const int* in_sizes, int n_in,
                              void* d_out, int out_size) {
    const float* nf   = (const float*)d_in[0];   // n_feats  [50000,128] f32
    const float* ew   = (const float*)d_in[1];   // e_weights[600000,1]  f32
    const float* W    = (const float*)d_in[2];   // W        [128,256]   f32
    const float* bias = (const float*)d_in[3];   // b        [128]       f32
    const int* src    = (const int*)d_in[4];     // src      [600000]    i32 or i64
    const int* dst    = (const int*)d_in[5];     // dst      [600000]    i32 or i64
    float* out        = (float*)d_out;           // [50000,128] f32

    zero_kernel<<<1024, 256>>>();
    transpose_kernel<<<(2 * D * D + 255) / 256, 256>>>(W);
    scatter_kernel<<<N_EDGES / 8, 256>>>(nf, ew, src, dst);
    gemm_kernel<<<(N_NODES + BM - 1) / BM, 256>>>(nf, bias, out);
}

// round 3
// speedup vs baseline: 1.2071x; 1.2071x over previous
#include <cuda_runtime.h>

#define N_NODES 50000
#define N_EDGES 600000
#define D 128
#define BM 64
#define BK 16
#define NKT ((2 * D) / BK)          // 16 k-tiles
#define ZPAD 4                      // BM+4 = 68 floats: keeps rows 16B-aligned

// Scratch (__device__ globals; no allocation allowed)
__device__ float g_agg[N_NODES * D];   // normalized aggregate (written fully by gather)
__device__ float g_Wt[2 * D * D];      // W^T [256][128]
__device__ int   g_cnt[N_NODES];       // in-degree
__device__ int   g_offs[N_NODES];      // CSR row starts
__device__ int   g_cursor[N_NODES];    // scatter cursors (copy of offs)
__device__ int   g_ssrc[N_EDGES];      // src sorted by dst
__device__ float g_sw[N_EDGES];        // weight sorted by dst

// ---- index dtype detection (values < 50000; int64 LE => odd words zero) ----
__device__ __forceinline__ bool idx_is64(const int* p) {
    return ((p[1] | p[3] | p[5] | p[7]) == 0);
}
__device__ __forceinline__ int edge_idx(const int* p, bool is64, int e) {
    return is64 ? (int)((const long long*)p)[e] : p[e];
}

// ---------------------------------------------------------------------------
__global__ void zero_cnt_kernel() {
    int i = blockIdx.x * blockDim.x + threadIdx.x;
    if (i < N_NODES) g_cnt[i] = 0;
}

__global__ void transpose_kernel(const float* __restrict__ W) {
    int idx = blockIdx.x * blockDim.x + threadIdx.x;
    if (idx < 2 * D * D) {
        int k = idx >> 7;
        int j = idx & 127;
        g_Wt[idx] = W[j * 2 * D + k];
    }
}

__global__ void hist_kernel(const int* __restrict__ dst) {
    int e = blockIdx.x * blockDim.x + threadIdx.x;
    if (e >= N_EDGES) return;
    bool is64 = idx_is64(dst);
    atomicAdd(&g_cnt[edge_idx(dst, is64, e)], 1);
}

// Single-block exclusive scan over 50K counts (Hillis-Steele on 1024 partials)
#define SCAN_T 1024
#define CHUNK ((N_NODES + SCAN_T - 1) / SCAN_T)   // 49
__global__ void scan_kernel() {
    __shared__ int sh[SCAN_T];
    int t = threadIdx.x;
    int start = t * CHUNK;
    int end = min(start + CHUNK, N_NODES);
    int s = 0;
    for (int i = start; i < end; i++) s += g_cnt[i];
    sh[t] = s;
    __syncthreads();
    for (int off = 1; off < SCAN_T; off <<= 1) {
        int v = (t >= off) ? sh[t - off] : 0;
        __syncthreads();
        sh[t] += v;
        __syncthreads();
    }
    int run = (t > 0) ? sh[t - 1] : 0;   // exclusive base
    for (int i = start; i < end; i++) {
        g_offs[i] = run;
        g_cursor[i] = run;
        run += g_cnt[i];
    }
}

__global__ void scatter_ids_kernel(const float* __restrict__ ew,
                                   const int* __restrict__ src,
                                   const int* __restrict__ dst) {
    int e = blockIdx.x * blockDim.x + threadIdx.x;
    if (e >= N_EDGES) return;
    bool s64 = idx_is64(src);
    bool d64 = idx_is64(dst);
    int s = edge_idx(src, s64, e);
    int d = edge_idx(dst, d64, e);
    int pos = atomicAdd(&g_cursor[d], 1);
    g_ssrc[pos] = s;
    g_sw[pos] = ew[e];
}

// Warp-per-node gather: lane l owns features [4l, 4l+4); coalesced 512B row reads
__global__ void gather_kernel(const float* __restrict__ nf) {
    int w = (blockIdx.x * blockDim.x + threadIdx.x) >> 5;
    int lane = threadIdx.x & 31;
    if (w >= N_NODES) return;
    int beg = g_offs[w];
    int deg = g_cnt[w];
    float4 acc = make_float4(0.f, 0.f, 0.f, 0.f);
    #pragma unroll 2
    for (int i = 0; i < deg; i++) {
        int s = g_ssrc[beg + i];
        float wt = g_sw[beg + i];
        float4 v = ((const float4*)nf)[s * (D / 4) + lane];
        acc.x += v.x * wt;
        acc.y += v.y * wt;
        acc.z += v.z * wt;
        acc.w += v.w * wt;
    }
    float inv = (deg > 0) ? (1.0f / (float)deg) : 0.0f;
    acc.x *= inv; acc.y *= inv; acc.z *= inv; acc.w *= inv;
    ((float4*)g_agg)[w * (D / 4) + lane] = acc;
}

// ---------------------------------------------------------------------------
// GEMM: out[n][j] = sum_k z[n][k] * Wt[k][j] + b[j]
//   z[n][k] = (k < 128) ? g_agg[n][k] : nf[n][k-128]   (agg pre-normalized)
// 64 nodes x 128 cols per block, 256 threads; warp rg owns rows [8rg,8rg+8),
// lane owns cols [4l,4l+4). Double-buffered smem, transposed z tile so the
// inner loop is 3 broadcast/vector LDS + 32 FFMA per kk.
// ---------------------------------------------------------------------------
__global__ __launch_bounds__(256, 4)
void gemm_kernel(const float* __restrict__ nf,
                 const float* __restrict__ bias,
                 float* __restrict__ out) {
    __shared__ float zs[2][BK][BM + ZPAD];   // 2*16*68*4  = 8704 B
    __shared__ float ws[2][BK][D];           // 2*16*128*4 = 16384 B

    int tx   = threadIdx.x;
    int lane = tx & 31;
    int rg   = tx >> 5;
    int n0   = blockIdx.x * BM;

    float acc[8][4];
    #pragma unroll
    for (int i = 0; i < 8; i++)
        #pragma unroll
        for (int c = 0; c < 4; c++) acc[i][c] = 0.f;

    // z-tile load map: node = tx>>2 (0..63), kq = tx&3 (float4 slot of 16 k)
    int z_node = tx >> 2;
    int z_kq   = tx & 3;
    int zn     = n0 + z_node;
    int znn    = (zn < N_NODES) ? zn : 0;

    // ---- prologue: tile 0 direct to smem buf 0 ----
    {
        const float4* srcp = (const float4*)(g_agg + (long long)znn * D);
        float4 v = srcp[z_kq];       // k0 = 0
        zs[0][z_kq * 4 + 0][z_node] = v.x;
        zs[0][z_kq * 4 + 1][z_node] = v.y;
        zs[0][z_kq * 4 + 2][z_node] = v.z;
        zs[0][z_kq * 4 + 3][z_node] = v.w;
        #pragma unroll
        for (int r = 0; r < 2; r++) {
            int i  = tx + r * 256;
            int k  = i >> 5;
            int jq = i & 31;
            *(float4*)(&ws[0][k][jq * 4]) = *(const float4*)(g_Wt + (long long)k * D + jq * 4);
        }
    }
    __syncthreads();

    for (int kt = 0; kt < NKT; kt++) {
        int b = kt & 1;
        float4 zv;
        float4 wv0, wv1;
        if (kt + 1 < NKT) {
            int k0 = (kt + 1) * BK;
            const float* base = (k0 < D) ? (g_agg + (long long)znn * D + k0)
                                         : (nf + (long long)znn * D + (k0 - D));
            zv = ((const float4*)base)[z_kq];
            {
                int i = tx, k = i >> 5, jq = i & 31;
                wv0 = *(const float4*)(g_Wt + (long long)(k0 + k) * D + jq * 4);
            }
            {
                int i = tx + 256, k = i >> 5, jq = i & 31;
                wv1 = *(const float4*)(g_Wt + (long long)(k0 + k) * D + jq * 4);
            }
        }

        // ---- compute on buffer b ----
        #pragma unroll
        for (int kk = 0; kk < BK; kk++) {
            float4 wv = *(const float4*)(&ws[b][kk][lane * 4]);
            float4 z0 = *(const float4*)(&zs[b][kk][rg * 8]);
            float4 z1 = *(const float4*)(&zs[b][kk][rg * 8 + 4]);
            float zr[8] = {z0.x, z0.y, z0.z, z0.w, z1.x, z1.y, z1.z, z1.w};
            #pragma unroll
            for (int i = 0; i < 8; i++) {
                acc[i][0] += zr[i] * wv.x;
                acc[i][1] += zr[i] * wv.y;
                acc[i][2] += zr[i] * wv.z;
                acc[i][3] += zr[i] * wv.w;
            }
        }

        if (kt + 1 < NKT) {
            int nb = b ^ 1;
            zs[nb][z_kq * 4 + 0][z_node] = zv.x;
            zs[nb][z_kq * 4 + 1][z_node] = zv.y;
            zs[nb][z_kq * 4 + 2][z_node] = zv.z;
            zs[nb][z_kq * 4 + 3][z_node] = zv.w;
            {
                int i = tx, k = i >> 5, jq = i & 31;
                *(float4*)(&ws[nb][k][jq * 4]) = wv0;
            }
            {
                int i = tx + 256, k = i >> 5, jq = i & 31;
                *(float4*)(&ws[nb][k][jq * 4]) = wv1;
            }
        }
        __syncthreads();
    }

    // ---- epilogue ----
    float4 bv = *(const float4*)(bias + lane * 4);
    #pragma unroll
    for (int i = 0; i < 8; i++) {
        int n = n0 + rg * 8 + i;
        if (n < N_NODES) {
            float4 o;
            o.x = acc[i][0] + bv.x;
            o.y = acc[i][1] + bv.y;
            o.z = acc[i][2] + bv.z;
            o.w = acc[i][3] + bv.w;
            *(float4*)(out + (long long)n * D + lane * 4) = o;
        }
    }
}

// ---------------------------------------------------------------------------
extern "C" void kernel_launch(void* const* d_in, const int* in_sizes, int n_in,
                              void* d_out, int out_size) {
    const float* nf   = (const float*)d_in[0];
    const float* ew   = (const float*)d_in[1];
    const float* W    = (const float*)d_in[2];
    const float* bias = (const float*)d_in[3];
    const int* src    = (const int*)d_in[4];
    const int* dst    = (const int*)d_in[5];
    float* out        = (float*)d_out;

    zero_cnt_kernel<<<(N_NODES + 255) / 256, 256>>>();
    transpose_kernel<<<(2 * D * D + 255) / 256, 256>>>(W);
    hist_kernel<<<(N_EDGES + 255) / 256, 256>>>(dst);
    scan_kernel<<<1, SCAN_T>>>();
    scatter_ids_kernel<<<(N_EDGES + 255) / 256, 256>>>(ew, src, dst);
    gather_kernel<<<(N_NODES * 32 + 255) / 256, 256>>>(nf);
    gemm_kernel<<<(N_NODES + BM - 1) / BM, 256>>>(nf, bias, out);
}

// round 6
// speedup vs baseline: 1.7821x; 1.4764x over previous
#include <cuda_runtime.h>

#define N_NODES 50000
#define N_EDGES 600000
#define D 128
#define BM 64
#define BK 16
#define NKT ((2 * D) / BK)          // 16 k-tiles
#define ZPAD 4

#define SCAN_BT 256
#define SCAN_NB ((N_NODES + SCAN_BT - 1) / SCAN_BT)   // 196

// Scratch (__device__ globals; no allocation allowed)
__device__ float g_agg[N_NODES * D];
__device__ float g_Wt[2 * D * D];
__device__ int   g_cnt[N_NODES];
__device__ int   g_offs[N_NODES];
__device__ int   g_cursor[N_NODES];
__device__ int   g_bsum[SCAN_NB];
__device__ int   g_bbase[SCAN_NB];
__device__ int   g_ssrc[N_EDGES];
__device__ float g_sw[N_EDGES];

// ---- index dtype detection (values < 50000; int64 LE => odd words zero) ----
__device__ __forceinline__ bool idx_is64(const int* p) {
    return ((p[1] | p[3] | p[5] | p[7]) == 0);
}
__device__ __forceinline__ int edge_idx(const int* p, bool is64, int e) {
    return is64 ? (int)((const long long*)p)[e] : p[e];
}

// ---------------------------------------------------------------------------
// Fused init: zero counts + transpose W (32768 + 50000 elems)
// ---------------------------------------------------------------------------
__global__ void init_kernel(const float* __restrict__ W) {
    int idx = blockIdx.x * blockDim.x + threadIdx.x;
    if (idx < 2 * D * D) {
        int k = idx >> 7;
        int j = idx & 127;
        g_Wt[idx] = W[j * 2 * D + k];
    }
    if (idx < N_NODES) g_cnt[idx] = 0;
}

__global__ void hist_kernel(const int* __restrict__ dst) {
    int e = blockIdx.x * blockDim.x + threadIdx.x;
    if (e >= N_EDGES) return;
    bool is64 = idx_is64(dst);
    atomicAdd(&g_cnt[edge_idx(dst, is64, e)], 1);
}

// ---------------------------------------------------------------------------
// 3-pass exclusive scan of g_cnt[50000] -> g_offs / g_cursor
// ---------------------------------------------------------------------------
__global__ void scan_pass1() {
    __shared__ int sh[SCAN_BT];
    int t = threadIdx.x;
    int i = blockIdx.x * SCAN_BT + t;
    int v = (i < N_NODES) ? g_cnt[i] : 0;
    sh[t] = v;
    __syncthreads();
    #pragma unroll
    for (int off = 1; off < SCAN_BT; off <<= 1) {
        int u = (t >= off) ? sh[t - off] : 0;
        __syncthreads();
        sh[t] += u;
        __syncthreads();
    }
    if (i < N_NODES) g_offs[i] = sh[t] - v;     // local exclusive prefix
    if (t == SCAN_BT - 1) g_bsum[blockIdx.x] = sh[t];
}

__global__ void scan_pass2() {
    __shared__ int sh[SCAN_BT];
    int t = threadIdx.x;
    int v = (t < SCAN_NB) ? g_bsum[t] : 0;
    sh[t] = v;
    __syncthreads();
    #pragma unroll
    for (int off = 1; off < SCAN_BT; off <<= 1) {
        int u = (t >= off) ? sh[t - off] : 0;
        __syncthreads();
        sh[t] += u;
        __syncthreads();
    }
    if (t < SCAN_NB) g_bbase[t] = sh[t] - v;    // exclusive block base
}

__global__ void scan_pass3() {
    int i = blockIdx.x * SCAN_BT + threadIdx.x;
    if (i >= N_NODES) return;
    int o = g_offs[i] + g_bbase[blockIdx.x];
    g_offs[i] = o;
    g_cursor[i] = o;
}

// ---------------------------------------------------------------------------
__global__ void scatter_ids_kernel(const float* __restrict__ ew,
                                   const int* __restrict__ src,
                                   const int* __restrict__ dst) {
    int e = blockIdx.x * blockDim.x + threadIdx.x;
    if (e >= N_EDGES) return;
    bool s64 = idx_is64(src);
    bool d64 = idx_is64(dst);
    int s = edge_idx(src, s64, e);
    int d = edge_idx(dst, d64, e);
    int pos = atomicAdd(&g_cursor[d], 1);
    g_ssrc[pos] = s;
    g_sw[pos] = ew[e];
}

// Warp-per-node gather: lane l owns features [4l, 4l+4)
__global__ void gather_kernel(const float* __restrict__ nf) {
    int w = (blockIdx.x * blockDim.x + threadIdx.x) >> 5;
    int lane = threadIdx.x & 31;
    if (w >= N_NODES) return;
    int beg = g_offs[w];
    int deg = g_cnt[w];
    float4 acc = make_float4(0.f, 0.f, 0.f, 0.f);
    #pragma unroll 2
    for (int i = 0; i < deg; i++) {
        int s = g_ssrc[beg + i];
        float wt = g_sw[beg + i];
        float4 v = ((const float4*)nf)[s * (D / 4) + lane];
        acc.x += v.x * wt;
        acc.y += v.y * wt;
        acc.z += v.z * wt;
        acc.w += v.w * wt;
    }
    float inv = (deg > 0) ? (1.0f / (float)deg) : 0.0f;
    acc.x *= inv; acc.y *= inv; acc.z *= inv; acc.w *= inv;
    ((float4*)g_agg)[w * (D / 4) + lane] = acc;
}

// ---------------------------------------------------------------------------
// GEMM: out[n][j] = sum_k z[n][k] * Wt[k][j] + b[j]
// ---------------------------------------------------------------------------
__global__ __launch_bounds__(256, 4)
void gemm_kernel(const float* __restrict__ nf,
                 const float* __restrict__ bias,
                 float* __restrict__ out) {
    __shared__ float zs[2][BK][BM + ZPAD];
    __shared__ float ws[2][BK][D];

    int tx   = threadIdx.x;
    int lane = tx & 31;
    int rg   = tx >> 5;
    int n0   = blockIdx.x * BM;

    float acc[8][4];
    #pragma unroll
    for (int i = 0; i < 8; i++)
        #pragma unroll
        for (int c = 0; c < 4; c++) acc[i][c] = 0.f;

    int z_node = tx >> 2;
    int z_kq   = tx & 3;
    int zn     = n0 + z_node;
    int znn    = (zn < N_NODES) ? zn : 0;

    // ---- prologue: tile 0 -> buf 0 ----
    {
        const float4* srcp = (const float4*)(g_agg + (long long)znn * D);
        float4 v = srcp[z_kq];
        zs[0][z_kq * 4 + 0][z_node] = v.x;
        zs[0][z_kq * 4 + 1][z_node] = v.y;
        zs[0][z_kq * 4 + 2][z_node] = v.z;
        zs[0][z_kq * 4 + 3][z_node] = v.w;
        #pragma unroll
        for (int r = 0; r < 2; r++) {
            int i  = tx + r * 256;
            int k  = i >> 5;
            int jq = i & 31;
            *(float4*)(&ws[0][k][jq * 4]) = *(const float4*)(g_Wt + (long long)k * D + jq * 4);
        }
    }
    __syncthreads();

    for (int kt = 0; kt < NKT; kt++) {
        int b = kt & 1;
        float4 zv;
        float4 wv0, wv1;
        if (kt + 1 < NKT) {
            int k0 = (kt + 1) * BK;
            const float* base = (k0 < D) ? (g_agg + (long long)znn * D + k0)
                                         : (nf + (long long)znn * D + (k0 - D));
            zv = ((const float4*)base)[z_kq];
            {
                int i = tx, k = i >> 5, jq = i & 31;
                wv0 = *(const float4*)(g_Wt + (long long)(k0 + k) * D + jq * 4);
            }
            {
                int i = tx + 256, k = i >> 5, jq = i & 31;
                wv1 = *(const float4*)(g_Wt + (long long)(k0 + k) * D + jq * 4);
            }
        }

        #pragma unroll
        for (int kk = 0; kk < BK; kk++) {
            float4 wv = *(const float4*)(&ws[b][kk][lane * 4]);
            float4 z0 = *(const float4*)(&zs[b][kk][rg * 8]);
            float4 z1 = *(const float4*)(&zs[b][kk][rg * 8 + 4]);
            float zr[8] = {z0.x, z0.y, z0.z, z0.w, z1.x, z1.y, z1.z, z1.w};
            #pragma unroll
            for (int i = 0; i < 8; i++) {
                acc[i][0] += zr[i] * wv.x;
                acc[i][1] += zr[i] * wv.y;
                acc[i][2] += zr[i] * wv.z;
                acc[i][3] += zr[i] * wv.w;
            }
        }

        if (kt + 1 < NKT) {
            int nb = b ^ 1;
            zs[nb][z_kq * 4 + 0][z_node] = zv.x;
            zs[nb][z_kq * 4 + 1][z_node] = zv.y;
            zs[nb][z_kq * 4 + 2][z_node] = zv.z;
            zs[nb][z_kq * 4 + 3][z_node] = zv.w;
            {
                int i = tx, k = i >> 5, jq = i & 31;
                *(float4*)(&ws[nb][k][jq * 4]) = wv0;
            }
            {
                int i = tx + 256, k = i >> 5, jq = i & 31;
                *(float4*)(&ws[nb][k][jq * 4]) = wv1;
            }
        }
        __syncthreads();
    }

    float4 bv = *(const float4*)(bias + lane * 4);
    #pragma unroll
    for (int i = 0; i < 8; i++) {
        int n = n0 + rg * 8 + i;
        if (n < N_NODES) {
            float4 o;
            o.x = acc[i][0] + bv.x;
            o.y = acc[i][1] + bv.y;
            o.z = acc[i][2] + bv.z;
            o.w = acc[i][3] + bv.w;
            *(float4*)(out + (long long)n * D + lane * 4) = o;
        }
    }
}

// ---------------------------------------------------------------------------
extern "C" void kernel_launch(void* const* d_in, const int* in_sizes, int n_in,
                              void* d_out, int out_size) {
    const float* nf   = (const float*)d_in[0];
    const float* ew   = (const float*)d_in[1];
    const float* W    = (const float*)d_in[2];
    const float* bias = (const float*)d_in[3];
    const int* src    = (const int*)d_in[4];
    const int* dst    = (const int*)d_in[5];
    float* out        = (float*)d_out;

    init_kernel<<<(N_NODES + 255) / 256, 256>>>(W);
    hist_kernel<<<(N_EDGES + 255) / 256, 256>>>(dst);
    scan_pass1<<<SCAN_NB, SCAN_BT>>>();
    scan_pass2<<<1, SCAN_BT>>>();
    scan_pass3<<<SCAN_NB, SCAN_BT>>>();
    scatter_ids_kernel<<<(N_EDGES + 255) / 256, 256>>>(ew, src, dst);
    gather_kernel<<<(N_NODES * 32 + 255) / 256, 256>>>(nf);
    gemm_kernel<<<(N_NODES + BM - 1) / BM, 256>>>(nf, bias, out);
}

// round 7
// speedup vs baseline: 2.0746x; 1.1642x over previous
#include <cuda_runtime.h>
#include <cstdint>

#define N_NODES 50000
#define N_EDGES 600000
#define D 128

#define SCAN_BT 256
#define SCAN_NB ((N_NODES + SCAN_BT - 1) / SCAN_BT)   // 196

// GEMM tile config
#define GBM 64
#define GBN 128
#define GBK 16
#define ZS_STRIDE (GBK + 4)    // 20: conflict-free A-frag reads + fills
#define WS_STRIDE (GBN + 8)    // 136: conflict-free B-frag reads + fills

// Scratch (__device__ globals; no allocation allowed)
__device__ float g_agg[N_NODES * D];
__device__ float g_Wt[2 * D * D];
__device__ int   g_cnt[N_NODES];
__device__ int   g_offs[N_NODES];
__device__ int   g_cursor[N_NODES];
__device__ int   g_bsum[SCAN_NB];
__device__ int   g_bbase[SCAN_NB];
__device__ int   g_ssrc[N_EDGES];
__device__ float g_sw[N_EDGES];

// ---- index dtype detection (values < 50000; int64 LE => odd words zero) ----
__device__ __forceinline__ bool idx_is64(const int* p) {
    return ((p[1] | p[3] | p[5] | p[7]) == 0);
}
__device__ __forceinline__ int edge_idx(const int* p, bool is64, int e) {
    return is64 ? (int)((const long long*)p)[e] : p[e];
}

// ---------------------------------------------------------------------------
__global__ void init_kernel(const float* __restrict__ W) {
    int idx = blockIdx.x * blockDim.x + threadIdx.x;
    if (idx < 2 * D * D) {
        int k = idx >> 7;
        int j = idx & 127;
        g_Wt[idx] = W[j * 2 * D + k];
    }
    if (idx < N_NODES) g_cnt[idx] = 0;
}

__global__ void hist_kernel(const int* __restrict__ dst) {
    int e = blockIdx.x * blockDim.x + threadIdx.x;
    if (e >= N_EDGES) return;
    bool is64 = idx_is64(dst);
    atomicAdd(&g_cnt[edge_idx(dst, is64, e)], 1);
}

// ---------------------------------------------------------------------------
// 3-pass exclusive scan of g_cnt[50000] -> g_offs / g_cursor
// ---------------------------------------------------------------------------
__global__ void scan_pass1() {
    __shared__ int sh[SCAN_BT];
    int t = threadIdx.x;
    int i = blockIdx.x * SCAN_BT + t;
    int v = (i < N_NODES) ? g_cnt[i] : 0;
    sh[t] = v;
    __syncthreads();
    #pragma unroll
    for (int off = 1; off < SCAN_BT; off <<= 1) {
        int u = (t >= off) ? sh[t - off] : 0;
        __syncthreads();
        sh[t] += u;
        __syncthreads();
    }
    if (i < N_NODES) g_offs[i] = sh[t] - v;
    if (t == SCAN_BT - 1) g_bsum[blockIdx.x] = sh[t];
}

__global__ void scan_pass2() {
    __shared__ int sh[SCAN_BT];
    int t = threadIdx.x;
    int v = (t < SCAN_NB) ? g_bsum[t] : 0;
    sh[t] = v;
    __syncthreads();
    #pragma unroll
    for (int off = 1; off < SCAN_BT; off <<= 1) {
        int u = (t >= off) ? sh[t - off] : 0;
        __syncthreads();
        sh[t] += u;
        __syncthreads();
    }
    if (t < SCAN_NB) g_bbase[t] = sh[t] - v;
}

__global__ void scan_pass3() {
    int i = blockIdx.x * SCAN_BT + threadIdx.x;
    if (i >= N_NODES) return;
    int o = g_offs[i] + g_bbase[blockIdx.x];
    g_offs[i] = o;
    g_cursor[i] = o;
}

// ---------------------------------------------------------------------------
__global__ void scatter_ids_kernel(const float* __restrict__ ew,
                                   const int* __restrict__ src,
                                   const int* __restrict__ dst) {
    int e = blockIdx.x * blockDim.x + threadIdx.x;
    if (e >= N_EDGES) return;
    bool s64 = idx_is64(src);
    bool d64 = idx_is64(dst);
    int s = edge_idx(src, s64, e);
    int d = edge_idx(dst, d64, e);
    int pos = atomicAdd(&g_cursor[d], 1);
    g_ssrc[pos] = s;
    g_sw[pos] = ew[e];
}

// Warp-per-node gather: lane l owns features [4l, 4l+4)
__global__ void gather_kernel(const float* __restrict__ nf) {
    int w = (blockIdx.x * blockDim.x + threadIdx.x) >> 5;
    int lane = threadIdx.x & 31;
    if (w >= N_NODES) return;
    int beg = g_offs[w];
    int deg = g_cnt[w];
    float4 acc = make_float4(0.f, 0.f, 0.f, 0.f);
    #pragma unroll 2
    for (int i = 0; i < deg; i++) {
        int s = g_ssrc[beg + i];
        float wt = g_sw[beg + i];
        float4 v = ((const float4*)nf)[s * (D / 4) + lane];
        acc.x += v.x * wt;
        acc.y += v.y * wt;
        acc.z += v.z * wt;
        acc.w += v.w * wt;
    }
    float inv = (deg > 0) ? (1.0f / (float)deg) : 0.0f;
    acc.x *= inv; acc.y *= inv; acc.z *= inv; acc.w *= inv;
    ((float4*)g_agg)[w * (D / 4) + lane] = acc;
}

// ---------------------------------------------------------------------------
// tf32 tensor-core GEMM with 3-term precision split.
// out[n][j] = sum_k z[n][k] * Wt[k][j] + b[j]
//   z[n][k] = (k < 128) ? g_agg[n][k] : nf[n][k-128]
// Block: 64 rows x 128 cols, 256 threads = 8 warps (4 m-warps x 2 n-warps).
// Warp tile: 16 rows x 64 cols = 8 x m16n8 C tiles.
// ---------------------------------------------------------------------------
__device__ __forceinline__ void f32_split_tf32(float x, uint32_t& hi, uint32_t& lo) {
    asm("cvt.rna.tf32.f32 %0, %1;" : "=r"(hi) : "f"(x));
    float lof = x - __uint_as_float(hi);
    asm("cvt.rna.tf32.f32 %0, %1;" : "=r"(lo) : "f"(lof));
}

__device__ __forceinline__ void mma_tf32(float* c, const uint32_t* a,
                                         uint32_t b0, uint32_t b1) {
    asm volatile(
        "mma.sync.aligned.m16n8k8.row.col.f32.tf32.tf32.f32 "
        "{%0,%1,%2,%3}, {%4,%5,%6,%7}, {%8,%9}, {%0,%1,%2,%3};"
        : "+f"(c[0]), "+f"(c[1]), "+f"(c[2]), "+f"(c[3])
        : "r"(a[0]), "r"(a[1]), "r"(a[2]), "r"(a[3]), "r"(b0), "r"(b1));
}

__global__ __launch_bounds__(256)
void gemm_tf32_kernel(const float* __restrict__ nf,
                      const float* __restrict__ bias,
                      float* __restrict__ out) {
    __shared__ uint32_t zs[2][GBM][ZS_STRIDE];   // [hi/lo][m][k]  10240 B
    __shared__ uint32_t ws[2][GBK][WS_STRIDE];   // [hi/lo][k][j]  17408 B

    int tx   = threadIdx.x;
    int w    = tx >> 5;
    int lane = tx & 31;
    int g    = lane >> 2;     // groupID (0..7)
    int tig  = lane & 3;      // threadID_in_group (0..3)
    int mw   = (w >> 1) * 16; // warp row offset within block
    int nw   = (w & 1) * 64;  // warp col offset within block
    int n0   = blockIdx.x * GBM;

    float c[8][4];
    #pragma unroll
    for (int t = 0; t < 8; t++)
        #pragma unroll
        for (int i = 0; i < 4; i++) c[t][i] = 0.f;

    // fill maps
    int zk  = tx & 15;        // k within tile
    int zm0 = tx >> 4;        // m base (0..15), stride 16
    int wj  = tx & 127;       // j
    int wk0 = tx >> 7;        // k base (0..1), stride 2

    for (int kt = 0; kt < (2 * D) / GBK; kt++) {
        int k0 = kt * GBK;
        __syncthreads();   // protect previous-iteration smem reads

        // ---- fill z tile: 64 x 16, 4 elems/thread ----
        {
            const float* zb = (k0 < D) ? g_agg : nf;
            int koff = (k0 < D) ? k0 : (k0 - D);
            #pragma unroll
            for (int i = 0; i < 4; i++) {
                int m = zm0 + i * 16;
                int node = n0 + m;
                if (node >= N_NODES) node = 0;   // clamp; stores are guarded
                float v = zb[(long long)node * D + koff + zk];
                uint32_t hi, lo;
                f32_split_tf32(v, hi, lo);
                zs[0][m][zk] = hi;
                zs[1][m][zk] = lo;
            }
        }
        // ---- fill W tile: 16 x 128, 8 elems/thread ----
        {
            #pragma unroll
            for (int i = 0; i < 8; i++) {
                int k = wk0 + i * 2;
                float v = g_Wt[(long long)(k0 + k) * GBN + wj];
                uint32_t hi, lo;
                f32_split_tf32(v, hi, lo);
                ws[0][k][wj] = hi;
                ws[1][k][wj] = lo;
            }
        }
        __syncthreads();

        // ---- 2 k8-steps per tile ----
        #pragma unroll
        for (int s = 0; s < 2; s++) {
            int kb = s * 8;
            uint32_t ah[4], al[4];
            ah[0] = zs[0][mw + g    ][kb + tig    ];
            ah[1] = zs[0][mw + g + 8][kb + tig    ];
            ah[2] = zs[0][mw + g    ][kb + tig + 4];
            ah[3] = zs[0][mw + g + 8][kb + tig + 4];
            al[0] = zs[1][mw + g    ][kb + tig    ];
            al[1] = zs[1][mw + g + 8][kb + tig    ];
            al[2] = zs[1][mw + g    ][kb + tig + 4];
            al[3] = zs[1][mw + g + 8][kb + tig + 4];

            #pragma unroll
            for (int t = 0; t < 8; t++) {
                int nn = nw + t * 8 + g;
                uint32_t bh0 = ws[0][kb + tig    ][nn];
                uint32_t bh1 = ws[0][kb + tig + 4][nn];
                uint32_t bl0 = ws[1][kb + tig    ][nn];
                uint32_t bl1 = ws[1][kb + tig + 4][nn];
                mma_tf32(c[t], ah, bh0, bh1);   // hi*hi
                mma_tf32(c[t], al, bh0, bh1);   // lo*hi
                mma_tf32(c[t], ah, bl0, bl1);   // hi*lo
            }
        }
    }

    // ---- epilogue: bias + store (float2 per row per tile) ----
    int r0 = n0 + mw + g;
    int r1 = r0 + 8;
    #pragma unroll
    for (int t = 0; t < 8; t++) {
        int col = nw + t * 8 + 2 * tig;
        float2 bv = *(const float2*)(bias + col);
        if (r0 < N_NODES) {
            float2 o0 = make_float2(c[t][0] + bv.x, c[t][1] + bv.y);
            *(float2*)(out + (long long)r0 * GBN + col) = o0;
        }
        if (r1 < N_NODES) {
            float2 o1 = make_float2(c[t][2] + bv.x, c[t][3] + bv.y);
            *(float2*)(out + (long long)r1 * GBN + col) = o1;
        }
    }
}

// ---------------------------------------------------------------------------
extern "C" void kernel_launch(void* const* d_in, const int* in_sizes, int n_in,
                              void* d_out, int out_size) {
    const float* nf   = (const float*)d_in[0];
    const float* ew   = (const float*)d_in[1];
    const float* W    = (const float*)d_in[2];
    const float* bias = (const float*)d_in[3];
    const int* src    = (const int*)d_in[4];
    const int* dst    = (const int*)d_in[5];
    float* out        = (float*)d_out;

    init_kernel<<<(N_NODES + 255) / 256, 256>>>(W);
    hist_kernel<<<(N_EDGES + 255) / 256, 256>>>(dst);
    scan_pass1<<<SCAN_NB, SCAN_BT>>>();
    scan_pass2<<<1, SCAN_BT>>>();
    scan_pass3<<<SCAN_NB, SCAN_BT>>>();
    scatter_ids_kernel<<<(N_EDGES + 255) / 256, 256>>>(ew, src, dst);
    gather_kernel<<<(N_NODES * 32 + 255) / 256, 256>>>(nf);
    gemm_tf32_kernel<<<(N_NODES + GBM - 1) / GBM, 256>>>(nf, bias, out);
}

// round 8
// speedup vs baseline: 2.6203x; 1.2630x over previous
#include <cuda_runtime.h>
#include <cuda_bf16.h>
#include <cstdint>

#define N_NODES 50000
#define N_EDGES 600000
#define D 128

#define SCAN_BT 256
#define SCAN_NB ((N_NODES + SCAN_BT - 1) / SCAN_BT)   // 196

// GEMM tile config: 64 rows x 128 cols per block, 256 thr = 8 warps (4m x 2n)
#define GBM 64
#define GBN 128
#define NCHUNK 16                 // 256 K / 16 per chunk

// Scratch (__device__ globals; no allocation allowed)
__device__ float g_agg[N_NODES * D];
__device__ int   g_cnt[N_NODES];
__device__ int   g_offs[N_NODES];
__device__ int   g_cursor[N_NODES];
__device__ int   g_bsum[SCAN_NB];
__device__ int   g_bbase[SCAN_NB];
__device__ int   g_ssrc[N_EDGES];
__device__ float g_sw[N_EDGES];
// W pre-packed as bf16 hi/lo words in mma-fragment order:
// flat idx = chunk*1024 + tig*256 + n*2 + which;  word = {lo: W[n][kb], hi: W[n][kb+1]},
// kb = chunk*16 + tig*2 + which*8
__device__ __align__(16) uint32_t g_Wbh[NCHUNK * 1024];
__device__ __align__(16) uint32_t g_Wbl[NCHUNK * 1024];

// ---- index dtype detection (values < 50000; int64 LE => odd words zero) ----
__device__ __forceinline__ bool idx_is64(const int* p) {
    return ((p[1] | p[3] | p[5] | p[7]) == 0);
}
__device__ __forceinline__ int edge_idx(const int* p, bool is64, int e) {
    return is64 ? (int)((const long long*)p)[e] : p[e];
}

// ---- bf16 2-term split of a float pair, packed as bf16x2 words ----
// word layout: low half = element with lower k (x0), high half = x1.
__device__ __forceinline__ void splitpack2(float x0, float x1,
                                           uint32_t& h, uint32_t& l) {
    float h0 = __bfloat162float(__float2bfloat16_rn(x0));
    float h1 = __bfloat162float(__float2bfloat16_rn(x1));
    asm("cvt.rn.bf16x2.f32 %0, %1, %2;" : "=r"(h) : "f"(h1), "f"(h0));
    asm("cvt.rn.bf16x2.f32 %0, %1, %2;" : "=r"(l) : "f"(x1 - h1), "f"(x0 - h0));
}

// ---------------------------------------------------------------------------
// Fused init: zero counts + pack W into bf16 hi/lo fragment-order arrays
// ---------------------------------------------------------------------------
__global__ void init_kernel(const float* __restrict__ W) {
    int idx = blockIdx.x * blockDim.x + threadIdx.x;
    if (idx < NCHUNK * 1024) {
        int chunk = idx >> 10;
        int ww    = idx & 1023;
        int tigr  = ww >> 8;
        int n     = (ww >> 1) & 127;
        int which = ww & 1;
        int kb    = chunk * 16 + tigr * 2 + which * 8;
        float x0 = W[n * 2 * D + kb];
        float x1 = W[n * 2 * D + kb + 1];
        uint32_t h, l;
        splitpack2(x0, x1, h, l);
        g_Wbh[idx] = h;
        g_Wbl[idx] = l;
    }
    if (idx < N_NODES) g_cnt[idx] = 0;
}

__global__ void hist_kernel(const int* __restrict__ dst) {
    int e = blockIdx.x * blockDim.x + threadIdx.x;
    if (e >= N_EDGES) return;
    bool is64 = idx_is64(dst);
    atomicAdd(&g_cnt[edge_idx(dst, is64, e)], 1);
}

// ---------------------------------------------------------------------------
// 3-pass exclusive scan of g_cnt[50000] -> g_offs / g_cursor
// ---------------------------------------------------------------------------
__global__ void scan_pass1() {
    __shared__ int sh[SCAN_BT];
    int t = threadIdx.x;
    int i = blockIdx.x * SCAN_BT + t;
    int v = (i < N_NODES) ? g_cnt[i] : 0;
    sh[t] = v;
    __syncthreads();
    #pragma unroll
    for (int off = 1; off < SCAN_BT; off <<= 1) {
        int u = (t >= off) ? sh[t - off] : 0;
        __syncthreads();
        sh[t] += u;
        __syncthreads();
    }
    if (i < N_NODES) g_offs[i] = sh[t] - v;
    if (t == SCAN_BT - 1) g_bsum[blockIdx.x] = sh[t];
}

__global__ void scan_pass2() {
    __shared__ int sh[SCAN_BT];
    int t = threadIdx.x;
    int v = (t < SCAN_NB) ? g_bsum[t] : 0;
    sh[t] = v;
    __syncthreads();
    #pragma unroll
    for (int off = 1; off < SCAN_BT; off <<= 1) {
        int u = (t >= off) ? sh[t - off] : 0;
        __syncthreads();
        sh[t] += u;
        __syncthreads();
    }
    if (t < SCAN_NB) g_bbase[t] = sh[t] - v;
}

__global__ void scan_pass3() {
    int i = blockIdx.x * SCAN_BT + threadIdx.x;
    if (i >= N_NODES) return;
    int o = g_offs[i] + g_bbase[blockIdx.x];
    g_offs[i] = o;
    g_cursor[i] = o;
}

// ---------------------------------------------------------------------------
__global__ void scatter_ids_kernel(const float* __restrict__ ew,
                                   const int* __restrict__ src,
                                   const int* __restrict__ dst) {
    int e = blockIdx.x * blockDim.x + threadIdx.x;
    if (e >= N_EDGES) return;
    bool s64 = idx_is64(src);
    bool d64 = idx_is64(dst);
    int s = edge_idx(src, s64, e);
    int d = edge_idx(dst, d64, e);
    int pos = atomicAdd(&g_cursor[d], 1);
    g_ssrc[pos] = s;
    g_sw[pos] = ew[e];
}

// Warp-per-node gather: lane l owns features [4l, 4l+4)
__global__ void gather_kernel(const float* __restrict__ nf) {
    int w = (blockIdx.x * blockDim.x + threadIdx.x) >> 5;
    int lane = threadIdx.x & 31;
    if (w >= N_NODES) return;
    int beg = g_offs[w];
    int deg = g_cnt[w];
    float4 acc = make_float4(0.f, 0.f, 0.f, 0.f);
    #pragma unroll 2
    for (int i = 0; i < deg; i++) {
        int s = g_ssrc[beg + i];
        float wt = g_sw[beg + i];
        float4 v = ((const float4*)nf)[s * (D / 4) + lane];
        acc.x += v.x * wt;
        acc.y += v.y * wt;
        acc.z += v.z * wt;
        acc.w += v.w * wt;
    }
    float inv = (deg > 0) ? (1.0f / (float)deg) : 0.0f;
    acc.x *= inv; acc.y *= inv; acc.z *= inv; acc.w *= inv;
    ((float4*)g_agg)[w * (D / 4) + lane] = acc;
}

// ---------------------------------------------------------------------------
// bf16-split tensor-core GEMM, m16n8k16, double-buffered, fragment-packed smem.
// out[n][j] = sum_k z[n][k] * W[j][k] + b[j],
//   z[n][k] = (k < 128) ? g_agg[n][k] : nf[n][k-128]
// ---------------------------------------------------------------------------
__device__ __forceinline__ void mma_bf16(float* c, const uint32_t* a,
                                         uint32_t b0, uint32_t b1) {
    asm volatile(
        "mma.sync.aligned.m16n8k16.row.col.f32.bf16.bf16.f32 "
        "{%0,%1,%2,%3}, {%4,%5,%6,%7}, {%8,%9}, {%0,%1,%2,%3};"
        : "+f"(c[0]), "+f"(c[1]), "+f"(c[2]), "+f"(c[3])
        : "r"(a[0]), "r"(a[1]), "r"(a[2]), "r"(a[3]), "r"(b0), "r"(b1));
}

__global__ __launch_bounds__(256)
void gemm_bf16_kernel(const float* __restrict__ nf,
                      const float* __restrict__ bias,
                      float* __restrict__ out) {
    // A frags: [buf][mwg][lane*4 + slot]  (LDS.128 per thread, conflict-free)
    __shared__ __align__(16) uint32_t Ah[2][4][128];
    __shared__ __align__(16) uint32_t Al[2][4][128];
    // B frags: [buf][tig][n*2 + which]   (LDS.64 per tile; stride 264 -> cf)
    __shared__ __align__(16) uint32_t Bh[2][4][264];
    __shared__ __align__(16) uint32_t Bl[2][4][264];

    int tx   = threadIdx.x;
    int w    = tx >> 5;
    int lane = tx & 31;
    int g    = lane >> 2;
    int tig  = lane & 3;
    int mwg  = w >> 1;            // warp m-group: rows [16mwg, 16mwg+16)
    int nw   = (w & 1) * 64;      // warp n-offset
    int n0   = blockIdx.x * GBM;

    float c[8][4];
    #pragma unroll
    for (int t = 0; t < 8; t++)
        #pragma unroll
        for (int i = 0; i < 4; i++) c[t][i] = 0.f;

    // ---- A fill map: thread -> one float4 of z (row am, k-quad aq) ----
    int am = tx >> 2;             // 0..63
    int aq = tx & 3;              // float4 slot within 16-k chunk
    int anode = n0 + am;
    if (anode >= N_NODES) anode = 0;    // clamp; output stores are guarded
    // dest word addrs (flat within a buffer's 512 words) for k-words i0=2aq, i1=2aq+1
    int ar = am & 15, ag = ar & 7, ahalf = ar >> 3, amg = am >> 4;
    int i0 = 2 * aq, i1 = 2 * aq + 1;
    int ad0 = amg * 128 + (4 * ag + (i0 & 3)) * 4 + ahalf + 2 * (i0 >> 2);
    int ad1 = amg * 128 + (4 * ag + (i1 & 3)) * 4 + ahalf + 2 * (i1 >> 2);
    uint32_t* AhF = &Ah[0][0][0];       // flat: buf*512 + ad
    uint32_t* AlF = &Al[0][0][0];

    // ---- B copy map: 2 uint2 per thread per buffer ----
    const uint2* Wh2 = (const uint2*)g_Wbh;   // 512 uint2 per chunk
    const uint2* Wl2 = (const uint2*)g_Wbl;
    int t0row = tx >> 7;                 // 0..1 ; second copy goes to row+2
    int t0off = (2 * tx) & 255;

    // ---- prologue: chunk 0 -> buf 0 ----
    {
        float4 f = *(const float4*)(g_agg + (long long)anode * D + aq * 4);
        uint32_t h0, l0, h1, l1;
        splitpack2(f.x, f.y, h0, l0);
        splitpack2(f.z, f.w, h1, l1);
        AhF[ad0] = h0; AlF[ad0] = l0;
        AhF[ad1] = h1; AlF[ad1] = l1;
        uint2 bh0 = Wh2[tx], bh1 = Wh2[tx + 256];
        uint2 bl0 = Wl2[tx], bl1 = Wl2[tx + 256];
        *(uint2*)&Bh[0][t0row][t0off]     = bh0;
        *(uint2*)&Bh[0][t0row + 2][t0off] = bh1;
        *(uint2*)&Bl[0][t0row][t0off]     = bl0;
        *(uint2*)&Bl[0][t0row + 2][t0off] = bl1;
    }
    __syncthreads();

    for (int kt = 0; kt < NCHUNK; kt++) {
        int b = kt & 1;

        // ---- prefetch next chunk into registers ----
        float4 pf;
        uint2 ph0, ph1, pl0, pl1;
        if (kt + 1 < NCHUNK) {
            int k0 = (kt + 1) * 16;
            const float* zb = (k0 < D) ? (g_agg + k0) : (nf + (k0 - D));
            pf  = *(const float4*)(zb + (long long)anode * D + aq * 4);
            int cb = (kt + 1) * 512;
            ph0 = Wh2[cb + tx]; ph1 = Wh2[cb + tx + 256];
            pl0 = Wl2[cb + tx]; pl1 = Wl2[cb + tx + 256];
        }

        // ---- compute on buffer b ----
        uint4 a4h = *(const uint4*)&Ah[b][mwg][lane * 4];
        uint4 a4l = *(const uint4*)&Al[b][mwg][lane * 4];
        uint32_t ah[4] = {a4h.x, a4h.y, a4h.z, a4h.w};
        uint32_t al[4] = {a4l.x, a4l.y, a4l.z, a4l.w};
        #pragma unroll
        for (int t = 0; t < 8; t++) {
            int nn = nw + t * 8 + g;
            uint2 bh = *(const uint2*)&Bh[b][tig][nn * 2];
            uint2 bl = *(const uint2*)&Bl[b][tig][nn * 2];
            mma_bf16(c[t], ah, bh.x, bh.y);   // hi*hi
            mma_bf16(c[t], al, bh.x, bh.y);   // lo*hi
            mma_bf16(c[t], ah, bl.x, bl.y);   // hi*lo
        }

        // ---- store prefetched chunk into the other buffer ----
        if (kt + 1 < NCHUNK) {
            int nb = b ^ 1;
            uint32_t h0, l0, h1, l1;
            splitpack2(pf.x, pf.y, h0, l0);
            splitpack2(pf.z, pf.w, h1, l1);
            AhF[nb * 512 + ad0] = h0; AlF[nb * 512 + ad0] = l0;
            AhF[nb * 512 + ad1] = h1; AlF[nb * 512 + ad1] = l1;
            *(uint2*)&Bh[nb][t0row][t0off]     = ph0;
            *(uint2*)&Bh[nb][t0row + 2][t0off] = ph1;
            *(uint2*)&Bl[nb][t0row][t0off]     = pl0;
            *(uint2*)&Bl[nb][t0row + 2][t0off] = pl1;
        }
        __syncthreads();
    }

    // ---- epilogue: bias + store ----
    int r0 = n0 + mwg * 16 + g;
    int r1 = r0 + 8;
    #pragma unroll
    for (int t = 0; t < 8; t++) {
        int col = nw + t * 8 + 2 * tig;
        float2 bv = *(const float2*)(bias + col);
        if (r0 < N_NODES) {
            float2 o0 = make_float2(c[t][0] + bv.x, c[t][1] + bv.y);
            *(float2*)(out + (long long)r0 * GBN + col) = o0;
        }
        if (r1 < N_NODES) {
            float2 o1 = make_float2(c[t][2] + bv.x, c[t][3] + bv.y);
            *(float2*)(out + (long long)r1 * GBN + col) = o1;
        }
    }
}

// ---------------------------------------------------------------------------
extern "C" void kernel_launch(void* const* d_in, const int* in_sizes, int n_in,
                              void* d_out, int out_size) {
    const float* nf   = (const float*)d_in[0];
    const float* ew   = (const float*)d_in[1];
    const float* W    = (const float*)d_in[2];
    const float* bias = (const float*)d_in[3];
    const int* src    = (const int*)d_in[4];
    const int* dst    = (const int*)d_in[5];
    float* out        = (float*)d_out;

    init_kernel<<<(N_NODES + 255) / 256, 256>>>(W);
    hist_kernel<<<(N_EDGES + 255) / 256, 256>>>(dst);
    scan_pass1<<<SCAN_NB, SCAN_BT>>>();
    scan_pass2<<<1, SCAN_BT>>>();
    scan_pass3<<<SCAN_NB, SCAN_BT>>>();
    scatter_ids_kernel<<<(N_EDGES + 255) / 256, 256>>>(ew, src, dst);
    gather_kernel<<<(N_NODES * 32 + 255) / 256, 256>>>(nf);
    gemm_bf16_kernel<<<(N_NODES + GBM - 1) / GBM, 256>>>(nf, bias, out);
}

// round 10
// speedup vs baseline: 2.7263x; 1.0405x over previous
#include <cuda_runtime.h>
#include <cuda_bf16.h>
#include <cstdint>

#define N_NODES 50000
#define N_EDGES 600000
#define D 128

#define SCAN_BT 256
#define SCAN_NB ((N_NODES + SCAN_BT - 1) / SCAN_BT)   // 196

// GEMM tile config: 64 rows x 128 cols per block, 256 thr = 8 warps (4m x 2n)
#define GBM 64
#define GBN 128
#define NCHUNK 16                 // 256 K / 16 per chunk

// Scratch (__device__ globals; no allocation allowed)
__device__ float g_agg[N_NODES * D];
__device__ int   g_cnt[N_NODES];
__device__ int   g_offs[N_NODES];
__device__ int   g_cursor[N_NODES];
__device__ int   g_bsum[SCAN_NB];
__device__ int   g_ssrc[N_EDGES];
__device__ float g_sw[N_EDGES];
// W pre-packed as bf16 hi/lo words in mma-fragment order:
// flat idx = chunk*1024 + tig*256 + n*2 + which;  word = {lo: W[n][kb], hi: W[n][kb+1]},
// kb = chunk*16 + tig*2 + which*8
__device__ __align__(16) uint32_t g_Wbh[NCHUNK * 1024];
__device__ __align__(16) uint32_t g_Wbl[NCHUNK * 1024];

// ---- index dtype detection (values < 50000; int64 LE => odd words zero) ----
__device__ __forceinline__ bool idx_is64(const int* p) {
    return ((p[1] | p[3] | p[5] | p[7]) == 0);
}
__device__ __forceinline__ int edge_idx(const int* p, bool is64, int e) {
    return is64 ? (int)((const long long*)p)[e] : p[e];
}

// ---- bf16 2-term split of a float pair, packed as bf16x2 words ----
__device__ __forceinline__ void splitpack2(float x0, float x1,
                                           uint32_t& h, uint32_t& l) {
    float h0 = __bfloat162float(__float2bfloat16_rn(x0));
    float h1 = __bfloat162float(__float2bfloat16_rn(x1));
    asm("cvt.rn.bf16x2.f32 %0, %1, %2;" : "=r"(h) : "f"(h1), "f"(h0));
    asm("cvt.rn.bf16x2.f32 %0, %1, %2;" : "=r"(l) : "f"(x1 - h1), "f"(x0 - h0));
}

// ---------------------------------------------------------------------------
// Fused init: zero counts + pack W into bf16 hi/lo fragment-order arrays
// ---------------------------------------------------------------------------
__global__ void init_kernel(const float* __restrict__ W) {
    int idx = blockIdx.x * blockDim.x + threadIdx.x;
    if (idx < NCHUNK * 1024) {
        int chunk = idx >> 10;
        int ww    = idx & 1023;
        int tigr  = ww >> 8;
        int n     = (ww >> 1) & 127;
        int which = ww & 1;
        int kb    = chunk * 16 + tigr * 2 + which * 8;
        float x0 = W[n * 2 * D + kb];
        float x1 = W[n * 2 * D + kb + 1];
        uint32_t h, l;
        splitpack2(x0, x1, h, l);
        g_Wbh[idx] = h;
        g_Wbl[idx] = l;
    }
    if (idx < N_NODES) g_cnt[idx] = 0;
}

__global__ void hist_kernel(const int* __restrict__ dst) {
    int e = blockIdx.x * blockDim.x + threadIdx.x;
    if (e >= N_EDGES) return;
    bool is64 = idx_is64(dst);
    atomicAdd(&g_cnt[edge_idx(dst, is64, e)], 1);
}

// ---------------------------------------------------------------------------
// 2-pass exclusive scan of g_cnt[50000] -> g_offs / g_cursor
// pass1: per-block scan + block sums. pass23: every block redundantly scans
// the 196 block sums in smem, then applies its base (fuses old pass2+pass3).
// ---------------------------------------------------------------------------
__global__ void scan_pass1() {
    __shared__ int sh[SCAN_BT];
    int t = threadIdx.x;
    int i = blockIdx.x * SCAN_BT + t;
    int v = (i < N_NODES) ? g_cnt[i] : 0;
    sh[t] = v;
    __syncthreads();
    #pragma unroll
    for (int off = 1; off < SCAN_BT; off <<= 1) {
        int u = (t >= off) ? sh[t - off] : 0;
        __syncthreads();
        sh[t] += u;
        __syncthreads();
    }
    if (i < N_NODES) g_offs[i] = sh[t] - v;
    if (t == SCAN_BT - 1) g_bsum[blockIdx.x] = sh[t];
}

__global__ void scan_pass23() {
    __shared__ int sh[SCAN_BT];
    int t = threadIdx.x;
    int v = (t < SCAN_NB) ? g_bsum[t] : 0;
    sh[t] = v;
    __syncthreads();
    #pragma unroll
    for (int off = 1; off < SCAN_BT; off <<= 1) {
        int u = (t >= off) ? sh[t - off] : 0;
        __syncthreads();
        sh[t] += u;
        __syncthreads();
    }
    int base = (blockIdx.x > 0) ? sh[blockIdx.x - 1] : 0;   // exclusive block base
    int i = blockIdx.x * SCAN_BT + t;
    if (i < N_NODES) {
        int o = g_offs[i] + base;
        g_offs[i] = o;
        g_cursor[i] = o;
    }
}

// ---------------------------------------------------------------------------
__global__ void scatter_ids_kernel(const float* __restrict__ ew,
                                   const int* __restrict__ src,
                                   const int* __restrict__ dst) {
    int e = blockIdx.x * blockDim.x + threadIdx.x;
    if (e >= N_EDGES) return;
    bool s64 = idx_is64(src);
    bool d64 = idx_is64(dst);
    int s = edge_idx(src, s64, e);
    int d = edge_idx(dst, d64, e);
    int pos = atomicAdd(&g_cursor[d], 1);
    g_ssrc[pos] = s;
    g_sw[pos] = ew[e];
}

// Warp-per-node gather, unroll-4: batch index loads, 4 independent row loads
__global__ void gather_kernel(const float* __restrict__ nf) {
    int w = (blockIdx.x * blockDim.x + threadIdx.x) >> 5;
    int lane = threadIdx.x & 31;
    if (w >= N_NODES) return;
    int beg = g_offs[w];
    int deg = g_cnt[w];
    const float4* nf4 = (const float4*)nf;
    float4 acc = make_float4(0.f, 0.f, 0.f, 0.f);

    int i = 0;
    for (; i + 4 <= deg; i += 4) {
        int   s0 = g_ssrc[beg + i];
        int   s1 = g_ssrc[beg + i + 1];
        int   s2 = g_ssrc[beg + i + 2];
        int   s3 = g_ssrc[beg + i + 3];
        float w0 = g_sw[beg + i];
        float w1 = g_sw[beg + i + 1];
        float w2 = g_sw[beg + i + 2];
        float w3 = g_sw[beg + i + 3];
        float4 v0 = nf4[s0 * (D / 4) + lane];
        float4 v1 = nf4[s1 * (D / 4) + lane];
        float4 v2 = nf4[s2 * (D / 4) + lane];
        float4 v3 = nf4[s3 * (D / 4) + lane];
        acc.x += v0.x * w0; acc.y += v0.y * w0; acc.z += v0.z * w0; acc.w += v0.w * w0;
        acc.x += v1.x * w1; acc.y += v1.y * w1; acc.z += v1.z * w1; acc.w += v1.w * w1;
        acc.x += v2.x * w2; acc.y += v2.y * w2; acc.z += v2.z * w2; acc.w += v2.w * w2;
        acc.x += v3.x * w3; acc.y += v3.y * w3; acc.z += v3.z * w3; acc.w += v3.w * w3;
    }
    for (; i < deg; i++) {
        int s = g_ssrc[beg + i];
        float wt = g_sw[beg + i];
        float4 v = nf4[s * (D / 4) + lane];
        acc.x += v.x * wt; acc.y += v.y * wt; acc.z += v.z * wt; acc.w += v.w * wt;
    }
    float inv = (deg > 0) ? (1.0f / (float)deg) : 0.0f;
    acc.x *= inv; acc.y *= inv; acc.z *= inv; acc.w *= inv;
    ((float4*)g_agg)[w * (D / 4) + lane] = acc;
}

// ---------------------------------------------------------------------------
// bf16-split tensor-core GEMM, m16n8k16, double-buffered, fragment-packed smem.
// ---------------------------------------------------------------------------
__device__ __forceinline__ void mma_bf16(float* c, const uint32_t* a,
                                         uint32_t b0, uint32_t b1) {
    asm volatile(
        "mma.sync.aligned.m16n8k16.row.col.f32.bf16.bf16.f32 "
        "{%0,%1,%2,%3}, {%4,%5,%6,%7}, {%8,%9}, {%0,%1,%2,%3};"
        : "+f"(c[0]), "+f"(c[1]), "+f"(c[2]), "+f"(c[3])
        : "r"(a[0]), "r"(a[1]), "r"(a[2]), "r"(a[3]), "r"(b0), "r"(b1));
}

__global__ __launch_bounds__(256)
void gemm_bf16_kernel(const float* __restrict__ nf,
                      const float* __restrict__ bias,
                      float* __restrict__ out) {
    __shared__ __align__(16) uint32_t Ah[2][4][128];
    __shared__ __align__(16) uint32_t Al[2][4][128];
    __shared__ __align__(16) uint32_t Bh[2][4][264];
    __shared__ __align__(16) uint32_t Bl[2][4][264];

    int tx   = threadIdx.x;
    int w    = tx >> 5;
    int lane = tx & 31;
    int g    = lane >> 2;
    int tig  = lane & 3;
    int mwg  = w >> 1;
    int nw   = (w & 1) * 64;
    int n0   = blockIdx.x * GBM;

    float c[8][4];
    #pragma unroll
    for (int t = 0; t < 8; t++)
        #pragma unroll
        for (int i = 0; i < 4; i++) c[t][i] = 0.f;

    int am = tx >> 2;
    int aq = tx & 3;
    int anode = n0 + am;
    if (anode >= N_NODES) anode = 0;
    int ar = am & 15, ag = ar & 7, ahalf = ar >> 3, amg = am >> 4;
    int i0 = 2 * aq, i1 = 2 * aq + 1;
    int ad0 = amg * 128 + (4 * ag + (i0 & 3)) * 4 + ahalf + 2 * (i0 >> 2);
    int ad1 = amg * 128 + (4 * ag + (i1 & 3)) * 4 + ahalf + 2 * (i1 >> 2);
    uint32_t* AhF = &Ah[0][0][0];
    uint32_t* AlF = &Al[0][0][0];

    const uint2* Wh2 = (const uint2*)g_Wbh;
    const uint2* Wl2 = (const uint2*)g_Wbl;
    int t0row = tx >> 7;
    int t0off = (2 * tx) & 255;

    {
        float4 f = *(const float4*)(g_agg + (long long)anode * D + aq * 4);
        uint32_t h0, l0, h1, l1;
        splitpack2(f.x, f.y, h0, l0);
        splitpack2(f.z, f.w, h1, l1);
        AhF[ad0] = h0; AlF[ad0] = l0;
        AhF[ad1] = h1; AlF[ad1] = l1;
        uint2 bh0 = Wh2[tx], bh1 = Wh2[tx + 256];
        uint2 bl0 = Wl2[tx], bl1 = Wl2[tx + 256];
        *(uint2*)&Bh[0][t0row][t0off]     = bh0;
        *(uint2*)&Bh[0][t0row + 2][t0off] = bh1;
        *(uint2*)&Bl[0][t0row][t0off]     = bl0;
        *(uint2*)&Bl[0][t0row + 2][t0off] = bl1;
    }
    __syncthreads();

    for (int kt = 0; kt < NCHUNK; kt++) {
        int b = kt & 1;

        float4 pf;
        uint2 ph0, ph1, pl0, pl1;
        if (kt + 1 < NCHUNK) {
            int k0 = (kt + 1) * 16;
            const float* zb = (k0 < D) ? (g_agg + k0) : (nf + (k0 - D));
            pf  = *(const float4*)(zb + (long long)anode * D + aq * 4);
            int cb = (kt + 1) * 512;
            ph0 = Wh2[cb + tx]; ph1 = Wh2[cb + tx + 256];
            pl0 = Wl2[cb + tx]; pl1 = Wl2[cb + tx + 256];
        }

        uint4 a4h = *(const uint4*)&Ah[b][mwg][lane * 4];
        uint4 a4l = *(const uint4*)&Al[b][mwg][lane * 4];
        uint32_t ah[4] = {a4h.x, a4h.y, a4h.z, a4h.w};
        uint32_t al[4] = {a4l.x, a4l.y, a4l.z, a4l.w};
        #pragma unroll
        for (int t = 0; t < 8; t++) {
            int nn = nw + t * 8 + g;
            uint2 bh = *(const uint2*)&Bh[b][tig][nn * 2];
            uint2 bl = *(const uint2*)&Bl[b][tig][nn * 2];
            mma_bf16(c[t], ah, bh.x, bh.y);
            mma_bf16(c[t], al, bh.x, bh.y);
            mma_bf16(c[t], ah, bl.x, bl.y);
        }

        if (kt + 1 < NCHUNK) {
            int nb = b ^ 1;
            uint32_t h0, l0, h1, l1;
            splitpack2(pf.x, pf.y, h0, l0);
            splitpack2(pf.z, pf.w, h1, l1);
            AhF[nb * 512 + ad0] = h0; AlF[nb * 512 + ad0] = l0;
            AhF[nb * 512 + ad1] = h1; AlF[nb * 512 + ad1] = l1;
            *(uint2*)&Bh[nb][t0row][t0off]     = ph0;
            *(uint2*)&Bh[nb][t0row + 2][t0off] = ph1;
            *(uint2*)&Bl[nb][t0row][t0off]     = pl0;
            *(uint2*)&Bl[nb][t0row + 2][t0off] = pl1;
        }
        __syncthreads();
    }

    int r0 = n0 + mwg * 16 + g;
    int r1 = r0 + 8;
    #pragma unroll
    for (int t = 0; t < 8; t++) {
        int col = nw + t * 8 + 2 * tig;
        float2 bv = *(const float2*)(bias + col);
        if (r0 < N_NODES) {
            float2 o0 = make_float2(c[t][0] + bv.x, c[t][1] + bv.y);
            *(float2*)(out + (long long)r0 * GBN + col) = o0;
        }
        if (r1 < N_NODES) {
            float2 o1 = make_float2(c[t][2] + bv.x, c[t][3] + bv.y);
            *(float2*)(out + (long long)r1 * GBN + col) = o1;
        }
    }
}

// ---------------------------------------------------------------------------
extern "C" void kernel_launch(void* const* d_in, const int* in_sizes, int n_in,
                              void* d_out, int out_size) {
    const float* nf   = (const float*)d_in[0];
    const float* ew   = (const float*)d_in[1];
    const float* W    = (const float*)d_in[2];
    const float* bias = (const float*)d_in[3];
    const int* src    = (const int*)d_in[4];
    const int* dst    = (const int*)d_in[5];
    float* out        = (float*)d_out;

    init_kernel<<<(N_NODES + 255) / 256, 256>>>(W);
    hist_kernel<<<(N_EDGES + 255) / 256, 256>>>(dst);
    scan_pass1<<<SCAN_NB, SCAN_BT>>>();
    scan_pass23<<<SCAN_NB, SCAN_BT>>>();
    scatter_ids_kernel<<<(N_EDGES + 255) / 256, 256>>>(ew, src, dst);
    gather_kernel<<<(N_NODES * 32 + 255) / 256, 256>>>(nf);
    gemm_bf16_kernel<<<(N_NODES + GBM - 1) / GBM, 256>>>(nf, bias, out);
}